// round 16
// baseline (speedup 1.0000x reference)
#include <cuda_runtime.h>
#include <math.h>

#define SS 1024
#define KK 4
#define NBLK 1024       // block-per-row

// ---------------- scratch (no allocations allowed) ----------------
__device__ float g_ps[NBLK];               // per-block (per-row) lin values
__device__ unsigned int g_done = 0;        // monotonic ticket (never reset)

__device__ __forceinline__ float softplusf(float x) {
    if (x > 20.0f)  return x;
    if (x < -20.0f) return expf(x);
    return log1pf(expf(x));                // accurate: only 3 uniform scalars
}
__device__ __forceinline__ float dot4(float4 a, float4 b) {
    return a.x * b.x + a.y * b.y + a.z * b.z + a.w * b.w;
}
__device__ __forceinline__ float sum4(float4 a) { return a.x + a.y + a.z + a.w; }
__device__ __forceinline__ float4 exp4(float4 v) {
    float4 w; w.x = __expf(v.x); w.y = __expf(v.y); w.z = __expf(v.z); w.w = __expf(v.w);
    return w;
}

__global__ void __launch_bounds__(256) k_fused(
    const float* __restrict__ log_delta,
    const float* __restrict__ log_tau,
    const float* __restrict__ log_lambda,
    const float* __restrict__ E,
    const float* __restrict__ logPi,
    const int*   __restrict__ sC1,
    const int*   __restrict__ sC2,
    const float* __restrict__ recip,
    const int*   __restrict__ splits_c1,
    const int*   __restrict__ splits_c2,
    const float* __restrict__ log_q,
    const void*  __restrict__ is_leaf,
    const int*   __restrict__ rootp,
    float*       __restrict__ out)
{
    __shared__ float s_red[8][16];     // per-warp reduced partials (14 used)
    __shared__ float s_fin[16];        // block-level sums
    __shared__ unsigned int s_islast;

    const int tid  = threadIdx.x;      // thread owns float4 slice j4 = tid
    const int s    = blockIdx.x;       // one row per block
    const int warp = tid >> 5, lane = tid & 31;

    // ---- independent index loads first (roots of all chains) ----
    const int root = rootp[0];
    const int i1 = sC1[s], i2 = sC2[s];

    int c[8];
    #pragma unroll
    for (int k = 0; k < KK; k++) {
        c[k]     = splits_c1[root * KK + k];
        c[4 + k] = splits_c2[root * KK + k];
    }

    // ---- data slices (all L2-resident across replays) ----
    const float4 rv = ((const float4*)(recip + (size_t)s  * SS))[tid];
    const float4 r1 = ((const float4*)(recip + (size_t)i1 * SS))[tid];
    const float4 r2 = ((const float4*)(recip + (size_t)i2 * SS))[tid];
    const float4 ev = ((const float4*)E)[tid];
    float4 wv[8];
    #pragma unroll
    for (int k = 0; k < 8; k++)
        wv[k] = exp4(((const float4*)(logPi + (size_t)c[k] * SS))[tid]);

    // ---- uniform scalars ----
    const float delta = softplusf(log_delta[0]);
    const float tau   = softplusf(log_tau[0]);
    const float lam   = softplusf(log_lambda[0]);
    const float rs = 1.0f + delta + tau + lam;
    const float pS = 1.0f / rs, pD = delta / rs, pT = tau / rs, pL = lam / rs;

    const unsigned char* lbp = (const unsigned char*)is_leaf;
    const unsigned int*  lwp = (const unsigned int*)is_leaf;
    const bool leaf = (lbp[root] != 0) || (lwp[root] == 0x3F800000u);

    // ---- 14 dot partials over this thread's slice ----
    float acc[14];
    acc[0] = sum4(rv);
    acc[1] = dot4(rv, ev);
    #pragma unroll
    for (int k = 0; k < 8; k++) acc[2 + k] = dot4(rv, wv[k]);
    acc[10] = sum4(r1);
    acc[11] = dot4(r1, ev);
    acc[12] = sum4(r2);
    acc[13] = dot4(r2, ev);

    // ---- warp butterfly + cross-warp combine ----
    #pragma unroll
    for (int q = 0; q < 14; q++)
        #pragma unroll
        for (int o = 16; o > 0; o >>= 1)
            acc[q] += __shfl_xor_sync(0xffffffffu, acc[q], o);
    if (lane == 0)
        #pragma unroll
        for (int q = 0; q < 14; q++) s_red[warp][q] = acc[q];
    __syncthreads();
    if (tid < 14) {
        float t = 0.0f;
        #pragma unroll
        for (int w2 = 0; w2 < 8; w2++) t += s_red[w2][tid];
        s_fin[tid] = t;
    }
    __syncthreads();

    // ---- epilogue (warp 0): lanes 0..3 handle k; lane 0 adds sl ----
    if (warp == 0) {
        float lin = 0.0f;
        if (leaf) {
            if (lane == 0) lin = __expf(logPi[(size_t)root * SS + s]);
        } else {
            if (lane < 4) {
                const int k = lane;
                const float q = __expf(log_q[root * KK + k]);
                const float* rA = logPi + (size_t)c[k] * SS;
                const float* rB = logPi + (size_t)c[4 + k] * SS;
                float A  = __expf(rA[s]),  B  = __expf(rB[s]);
                float Af = __expf(rA[i1]), Ag = __expf(rA[i2]);
                float Bf = __expf(rB[i1]), Bg = __expf(rB[i2]);
                float inv = 1.0f / fmaxf(s_fin[0], 1.0f);
                float sA = s_fin[2 + k];
                float sB = s_fin[6 + k];
                lin = q * (pS * (Af * Bg + Ag * Bf)
                         + pD * (A * B)
                         + pT * inv * (A * sB + B * sA));
            }
            lin += __shfl_xor_sync(0xffffffffu, lin, 1);
            lin += __shfl_xor_sync(0xffffffffu, lin, 2);   // k-sum on lane 0
            if (lane == 0) {
                float inv1 = 1.0f / fmaxf(s_fin[10], 1.0f);
                float inv2 = 1.0f / fmaxf(s_fin[12], 1.0f);
                float E1 = E[i1], E2 = E[i2];
                float En1 = pL + pD * E1 * E1 + pT * E1 * (s_fin[11] * inv1)
                          + pS * E[sC1[i1]] * E[sC2[i1]];
                float En2 = pL + pD * E2 * E2 + pT * E2 * (s_fin[13] * inv2)
                          + pS * E[sC1[i2]] * E[sC2[i2]];
                float P1 = __expf(logPi[(size_t)root * SS + i1]);
                float P2 = __expf(logPi[(size_t)root * SS + i2]);
                lin += pS * (P1 * En2 + P2 * En1);
            }
        }
        if (lane == 0) g_ps[s] = lin;
    }

    // ---- ticket: last block does the final fixed-order sum ----
    __syncthreads();
    if (tid == 0) {
        __threadfence();                   // release g_ps[s]
        unsigned int prev = atomicAdd(&g_done, 1u);
        s_islast = ((prev % NBLK) == (unsigned int)(NBLK - 1)) ? 1u : 0u;
    }
    __syncthreads();
    if (!s_islast) return;
    __threadfence();                       // acquire: all partials visible

    // deterministic fixed-order sum of 1024 partials: thread t sums 4, then tree
    {
        __shared__ float s_sum[256];
        float v = g_ps[tid] + g_ps[tid + 256] + g_ps[tid + 512] + g_ps[tid + 768];
        s_sum[tid] = v;
        __syncthreads();
        for (int stride = 128; stride >= 32; stride >>= 1) {
            if (tid < stride) s_sum[tid] += s_sum[tid + stride];
            __syncthreads();
        }
        if (tid < 32) {
            float x = s_sum[tid];
            #pragma unroll
            for (int o = 16; o > 0; o >>= 1)
                x += __shfl_xor_sync(0xffffffffu, x, o);
            if (tid == 0) out[0] = logf(x);
        }
    }
}

// ---------------- launch ----------------
extern "C" void kernel_launch(void* const* d_in, const int* in_sizes, int n_in,
                              void* d_out, int out_size)
{
    const float* log_delta  = (const float*)d_in[0];
    const float* log_tau    = (const float*)d_in[1];
    const float* log_lambda = (const float*)d_in[2];
    const float* E          = (const float*)d_in[3];
    const float* log_Pi     = (const float*)d_in[4];
    const int*   s_C1       = (const int*)  d_in[5];
    const int*   s_C2       = (const int*)  d_in[6];
    const float* recip      = (const float*)d_in[7];
    const int*   splits_c1  = (const int*)  d_in[8];
    const int*   splits_c2  = (const int*)  d_in[9];
    const float* log_q      = (const float*)d_in[10];
    const void*  is_leaf    = (const void*) d_in[11];
    const int*   root_id    = (const int*)  d_in[12];
    float* out = (float*)d_out;

    k_fused<<<NBLK, 256>>>(log_delta, log_tau, log_lambda, E, log_Pi,
                           s_C1, s_C2, recip, splits_c1, splits_c2,
                           log_q, is_leaf, root_id, out);
}

// round 17
// speedup vs baseline: 1.4495x; 1.4495x over previous
#include <cuda_runtime.h>
#include <math.h>

#define SS 1024
#define CC 4096
#define KK 4
#define NB 128          // blocks (NB * 8 warps == SS rows)

// ---------------- scratch (no allocations allowed) ----------------
__device__ float g_ps[NB];                 // per-block partial sums
__device__ unsigned int g_done = 0;        // monotonic ticket (never reset)

__device__ __forceinline__ float softplusf(float x) {
    if (x > 20.0f)  return x;
    if (x < -20.0f) return expf(x);
    return log1pf(expf(x));            // accurate: only 3 uniform scalars
}

__global__ void __launch_bounds__(256) k_fused(
    const float* __restrict__ log_delta,
    const float* __restrict__ log_tau,
    const float* __restrict__ log_lambda,
    const float* __restrict__ E,
    const float* __restrict__ logPi,
    const int*   __restrict__ sC1,
    const int*   __restrict__ sC2,
    const float* __restrict__ recip,
    const int*   __restrict__ splits_c1,
    const int*   __restrict__ splits_c2,
    const float* __restrict__ log_q,
    const void*  __restrict__ is_leaf,
    const int*   __restrict__ rootp,
    float*       __restrict__ out)
{
    __shared__ float sw[8 * SS];   // exp'd split rows: 0..3 c1, 4..7 c2 (32 KB)
    __shared__ float sE[SS];       // E (4 KB)
    __shared__ float s_part[8];
    __shared__ unsigned int s_islast;

    const int tid  = threadIdx.x;
    const int b    = blockIdx.x;
    const int warp = tid >> 5, lane = tid & 31;
    const int s    = b * 8 + warp;

    // ---- issue all independent loads early (roots of every chain) ----
    const int i1 = sC1[s], i2 = sC2[s];
    const float4* rrow = (const float4*)(recip + (size_t)s * SS);
    float4 rv[8];
    #pragma unroll
    for (int it = 0; it < 8; it++) rv[it] = rrow[lane + it * 32];
    // second-level index gathers (local E_new recomputation)
    const int i1a = sC1[i1], i1b = sC2[i1];
    const int i2a = sC1[i2], i2b = sC2[i2];
    // aux row base pointers (loads issued in the aux loop; addresses ready now)
    const float4* r1p = (const float4*)(recip + (size_t)i1 * SS);
    const float4* r2p = (const float4*)(recip + (size_t)i2 * SS);

    // ---- scalar constants (uniform broadcasts) ----
    const int root = rootp[0];
    const float delta = softplusf(log_delta[0]);
    const float tau   = softplusf(log_tau[0]);
    const float lam   = softplusf(log_lambda[0]);
    const float rs = 1.0f + delta + tau + lam;
    const float pS = 1.0f / rs, pD = delta / rs, pT = tau / rs, pL = lam / rs;

    const unsigned char* lbp = (const unsigned char*)is_leaf;
    const unsigned int*  lwp = (const unsigned int*)is_leaf;
    const bool leaf = (lbp[root] != 0) || (lwp[root] == 0x3F800000u);

    // ---- stage 8 exp'd split rows + E in shared (root row NOT staged) ----
    #pragma unroll
    for (int k = 0; k < 8; k++) {
        int c = (k < 4) ? splits_c1[root * KK + k] : splits_c2[root * KK + (k - 4)];
        float4 v = ((const float4*)(logPi + (size_t)c * SS))[tid];
        float4 w;
        w.x = __expf(v.x); w.y = __expf(v.y); w.z = __expf(v.z); w.w = __expf(v.w);
        ((float4*)(sw + k * SS))[tid] = w;
    }
    ((float4*)sE)[tid] = ((const float4*)E)[tid];
    __syncthreads();

    // ---- dots: row s (10 accs) + rows i1, i2 (4 accs) ----
    float acc[14];
    #pragma unroll
    for (int q = 0; q < 14; q++) acc[q] = 0.0f;

    #pragma unroll
    for (int it = 0; it < 8; it++) {
        const int j4 = lane + it * 32;
        const float4 r = rv[it];
        const float4 ev = ((const float4*)sE)[j4];
        acc[0] += r.x + r.y + r.z + r.w;
        acc[1] += r.x * ev.x + r.y * ev.y + r.z * ev.z + r.w * ev.w;
        #pragma unroll
        for (int k = 0; k < 8; k++) {
            const float4 wv = ((const float4*)(sw + k * SS))[j4];
            acc[2 + k] += r.x * wv.x + r.y * wv.y + r.z * wv.z + r.w * wv.w;
        }
    }
    #pragma unroll
    for (int it = 0; it < 8; it++) {
        const int j4 = lane + it * 32;
        const float4 a = r1p[j4];
        const float4 c2v = r2p[j4];
        const float4 ev = ((const float4*)sE)[j4];
        acc[10] += a.x + a.y + a.z + a.w;
        acc[11] += a.x * ev.x + a.y * ev.y + a.z * ev.z + a.w * ev.w;
        acc[12] += c2v.x + c2v.y + c2v.z + c2v.w;
        acc[13] += c2v.x * ev.x + c2v.y * ev.y + c2v.z * ev.z + c2v.w * ev.w;
    }

    #pragma unroll
    for (int q = 0; q < 14; q++)
        #pragma unroll
        for (int o = 16; o > 0; o >>= 1)
            acc[q] += __shfl_xor_sync(0xffffffffu, acc[q], o);   // totals in ALL lanes

    const float inv = 1.0f / fmaxf(acc[0], 1.0f);

    // ---- fully local epilogue: lanes 0..3 handle k ----
    float lin_local = 0.0f;
    if (!leaf) {
        if (lane < 4) {
            const int k = lane;
            const float q = __expf(log_q[root * KK + k]);
            const float* PA = sw + k * SS;
            const float* PB = sw + (4 + k) * SS;
            float A  = PA[s],  B  = PB[s];
            float Af = PA[i1], Ag = PA[i2];
            float Bf = PB[i1], Bg = PB[i2];
            float sA = acc[2 + k];
            float sB = acc[6 + k];
            lin_local = q * (pS * (Af * Bg + Ag * Bf)
                           + pD * (A * B)
                           + (pT * inv) * (A * sB + B * sA));
        }
        lin_local += __shfl_xor_sync(0xffffffffu, lin_local, 1);
        lin_local += __shfl_xor_sync(0xffffffffu, lin_local, 2);  // k-sum on lane 0
    }

    // ---- sl term with LOCALLY recomputed E_new; root points via direct L2 gathers ----
    if (lane == 0) {
        float lin;
        if (leaf) {
            lin = __expf(logPi[(size_t)root * SS + s]);
        } else {
            float inv1 = 1.0f / fmaxf(acc[10], 1.0f);
            float inv2 = 1.0f / fmaxf(acc[12], 1.0f);
            float E1 = sE[i1], E2 = sE[i2];
            float En1 = pL + pD * E1 * E1 + pT * E1 * (acc[11] * inv1) + pS * sE[i1a] * sE[i1b];
            float En2 = pL + pD * E2 * E2 + pT * E2 * (acc[13] * inv2) + pS * sE[i2a] * sE[i2b];
            float P1 = __expf(logPi[(size_t)root * SS + i1]);
            float P2 = __expf(logPi[(size_t)root * SS + i2]);
            lin = lin_local + pS * (P1 * En2 + P2 * En1);
        }
        s_part[warp] = lin;
    }
    __syncthreads();
    if (tid == 0) {
        float t = 0.0f;
        #pragma unroll
        for (int w2 = 0; w2 < 8; w2++) t += s_part[w2];
        g_ps[b] = t;
        __threadfence();                       // release partial
        unsigned int prev = atomicAdd(&g_done, 1u);
        s_islast = ((prev % NB) == (unsigned int)(NB - 1)) ? 1u : 0u;
    }
    __syncthreads();
    if (!s_islast) return;
    __threadfence();                           // acquire: all partials visible

    // ---- last block: fixed-order deterministic final sum + one log ----
    if (warp == 0) {
        float v = g_ps[lane] + g_ps[lane + 32] + g_ps[lane + 64] + g_ps[lane + 96];
        #pragma unroll
        for (int o = 16; o > 0; o >>= 1)
            v += __shfl_xor_sync(0xffffffffu, v, o);
        if (lane == 0) out[0] = logf(v);
    }
}

// ---------------- launch ----------------
extern "C" void kernel_launch(void* const* d_in, const int* in_sizes, int n_in,
                              void* d_out, int out_size)
{
    const float* log_delta  = (const float*)d_in[0];
    const float* log_tau    = (const float*)d_in[1];
    const float* log_lambda = (const float*)d_in[2];
    const float* E          = (const float*)d_in[3];
    const float* log_Pi     = (const float*)d_in[4];
    const int*   s_C1       = (const int*)  d_in[5];
    const int*   s_C2       = (const int*)  d_in[6];
    const float* recip      = (const float*)d_in[7];
    const int*   splits_c1  = (const int*)  d_in[8];
    const int*   splits_c2  = (const int*)  d_in[9];
    const float* log_q      = (const float*)d_in[10];
    const void*  is_leaf    = (const void*) d_in[11];
    const int*   root_id    = (const int*)  d_in[12];
    float* out = (float*)d_out;

    k_fused<<<NB, 256>>>(log_delta, log_tau, log_lambda, E, log_Pi,
                         s_C1, s_C2, recip, splits_c1, splits_c2,
                         log_q, is_leaf, root_id, out);
}